// round 2
// baseline (speedup 1.0000x reference)
#include <cuda_runtime.h>
#include <cuda_bf16.h>

// Problem constants
#define Nn    50000
#define Dd    128
#define Rr    10
#define Ee    800000
#define NSEL  8192
#define NCc   12

// ---------------- device scratch (static allocations only) ----------------
__device__ float g_x[Nn * Dd];                       // 25.6 MB  current node features
__device__ float g_acc[Nn * Dd];                     // 25.6 MB  conv accumulator
__device__ float g_xw[(size_t)Nn * Rr * Dd];         // 256 MB   x @ W[r] for r=0..9
__device__ float g_W[(Rr + 1) * Dd * Dd];            // 0.7 MB   W[0..9] + root in slot 10
__device__ int   g_icnt[Rr * Nn];                    // 2 MB     per-(r,dst) edge counts
__device__ float g_inv[Rr * Nn];                     // 2 MB     1/max(cnt,1)
__device__ float g_hsel[NSEL * Dd];                  // 4 MB     classifier hidden

// ---------------- small kernels ----------------
__global__ void k_copy_x(const float* __restrict__ src) {
    int i = blockIdx.x * blockDim.x + threadIdx.x;
    if (i < Nn * Dd / 4) ((float4*)g_x)[i] = ((const float4*)src)[i];
}

__global__ void k_build_W(const float* __restrict__ comp,
                          const float* __restrict__ bases,
                          const float* __restrict__ root) {
    int i = blockIdx.x * blockDim.x + threadIdx.x;
    if (i >= (Rr + 1) * Dd * Dd) return;
    int slot = i >> 14;           // / 16384
    int idx  = i & 16383;
    float v;
    if (slot < Rr) {
        v = 0.f;
#pragma unroll
        for (int b = 0; b < 4; b++)
            v += comp[slot * 4 + b] * bases[b * Dd * Dd + idx];
    } else {
        v = root[idx];
    }
    g_W[i] = v;
}

__global__ void k_zero_cnt() {
    int i = blockIdx.x * blockDim.x + threadIdx.x;
    if (i < Rr * Nn) g_icnt[i] = 0;
}

__global__ void k_count(const int* __restrict__ ei, const int* __restrict__ et) {
    int e = blockIdx.x * blockDim.x + threadIdx.x;
    if (e >= Ee) return;
    atomicAdd(&g_icnt[et[e] * Nn + ei[Ee + e]], 1);
}

__global__ void k_inv() {
    int i = blockIdx.x * blockDim.x + threadIdx.x;
    if (i < Rr * Nn) g_inv[i] = 1.0f / fmaxf((float)g_icnt[i], 1.0f);
}

// one warp per edge; 128 floats = 32 lanes x float4; vector reduction into L2-resident acc
__global__ void k_scatter(const int* __restrict__ ei, const int* __restrict__ et) {
    int gt = blockIdx.x * blockDim.x + threadIdx.x;
    int e = gt >> 5;
    if (e >= Ee) return;
    int lane = gt & 31;
    int s = ei[e], t = ei[Ee + e], r = et[e];
    float w = g_inv[r * Nn + t];
    float4 v = *(const float4*)(g_xw + (size_t)s * (Rr * Dd) + r * Dd + lane * 4);
    v.x *= w; v.y *= w; v.z *= w; v.w *= w;
    float* p = g_acc + t * Dd + lane * 4;
    asm volatile("red.global.add.v4.f32 [%0], {%1,%2,%3,%4};"
                 :: "l"(p), "f"(v.x), "f"(v.y), "f"(v.z), "f"(v.w) : "memory");
}

// one warp per node: LayerNorm (+optional ReLU), g_acc -> g_x
__global__ void k_ln(const float* __restrict__ g, const float* __restrict__ b, int relu) {
    int gt = blockIdx.x * blockDim.x + threadIdx.x;
    int node = gt >> 5;
    if (node >= Nn) return;
    int lane = gt & 31;
    float4 v = ((const float4*)g_acc)[node * 32 + lane];
    float s = v.x + v.y + v.z + v.w;
    float q = v.x * v.x + v.y * v.y + v.z * v.z + v.w * v.w;
#pragma unroll
    for (int o = 16; o; o >>= 1) {
        s += __shfl_xor_sync(0xffffffffu, s, o);
        q += __shfl_xor_sync(0xffffffffu, q, o);
    }
    float mean = s * (1.f / 128.f);
    float var  = q * (1.f / 128.f) - mean * mean;
    float rstd = rsqrtf(var + 1e-5f);
    float4 gg = ((const float4*)g)[lane];
    float4 bb = ((const float4*)b)[lane];
    float4 o4;
    o4.x = (v.x - mean) * rstd * gg.x + bb.x;
    o4.y = (v.y - mean) * rstd * gg.y + bb.y;
    o4.z = (v.z - mean) * rstd * gg.z + bb.z;
    o4.w = (v.w - mean) * rstd * gg.w + bb.w;
    if (relu) {
        o4.x = fmaxf(o4.x, 0.f); o4.y = fmaxf(o4.y, 0.f);
        o4.z = fmaxf(o4.z, 0.f); o4.w = fmaxf(o4.w, 0.f);
    }
    ((float4*)g_x)[node * 32 + lane] = o4;
}

// final tiny GEMM: out[i,c] = hsel[i,:] @ Wc2[:,c] + bc2[c]
__global__ void k_final(const float* __restrict__ W, const float* __restrict__ b,
                        float* __restrict__ out) {
    int gt = blockIdx.x * blockDim.x + threadIdx.x;
    if (gt >= NSEL * NCc) return;
    int i = gt / NCc, c = gt % NCc;
    const float* hr = g_hsel + i * Dd;
    float s = b[c];
#pragma unroll 8
    for (int k = 0; k < Dd; k++) s += hr[k] * W[k * NCc + c];
    out[gt] = s;
}

// ---------------- generic 128x128-tile fp32 GEMM ----------------
// C tile: 128 rows x 128 cols, 256 threads, 8x8 register tile each.
// grid.y selects weight slot (B + y*K*128); y==rootY routes to Croot (+bias).
// aIdx: optional gather of A rows (int32). rowIdx: optional scatter of C rows (int32).
__global__ void __launch_bounds__(256)
gemm_k(const float* __restrict__ A, const int* __restrict__ aIdx,
       int M, int K,
       const float* __restrict__ B,
       float* __restrict__ C, int ldc,
       float* __restrict__ Croot, int rootY,
       const float* __restrict__ bias, int relu,
       const int* __restrict__ rowIdx) {
    int y = blockIdx.y;
    const float* Bz = B + (size_t)y * K * Dd;
    int row0 = blockIdx.x * 128;
    __shared__ float As[128][36];   // padded row stride (36 floats keeps 16B alignment)
    __shared__ float Bs[32][128];
    float acc[8][8];
#pragma unroll
    for (int i = 0; i < 8; i++)
#pragma unroll
        for (int j = 0; j < 8; j++) acc[i][j] = 0.f;

    int tid = threadIdx.x;
    int tx = tid & 15, ty = tid >> 4;

    for (int kb = 0; kb < K; kb += 32) {
        // A tile: 128x32 floats = 1024 float4
#pragma unroll
        for (int it = 0; it < 4; it++) {
            int idx = tid + it * 256;
            int m = idx >> 3;
            int kq = (idx & 7) * 4;
            float4 v = make_float4(0.f, 0.f, 0.f, 0.f);
            int row = row0 + m;
            if (row < M) {
                int ar = aIdx ? aIdx[row] : row;
                v = *(const float4*)&A[(size_t)ar * K + kb + kq];
            }
            *(float4*)&As[m][kq] = v;
        }
        // B tile: 32x128 floats = 1024 float4
#pragma unroll
        for (int it = 0; it < 4; it++) {
            int idx = tid + it * 256;
            int k = idx >> 5;
            int nq = (idx & 31) * 4;
            *(float4*)&Bs[k][nq] = *(const float4*)&Bz[(size_t)(kb + k) * Dd + nq];
        }
        __syncthreads();
#pragma unroll
        for (int k = 0; k < 32; k++) {
            float a[8], bb[8];
#pragma unroll
            for (int i = 0; i < 8; i++) a[i] = As[ty + 16 * i][k];
#pragma unroll
            for (int j = 0; j < 8; j++) bb[j] = Bs[k][tx + 16 * j];
#pragma unroll
            for (int i = 0; i < 8; i++)
#pragma unroll
                for (int j = 0; j < 8; j++) acc[i][j] += a[i] * bb[j];
        }
        __syncthreads();
    }

    bool isRoot = (y == rootY);
    float* Cout = isRoot ? Croot : C;
    int ldcO   = isRoot ? Dd : ldc;
    int colOff = isRoot ? 0  : y * Dd;
    bool useBias = (rootY < 0) || isRoot;
#pragma unroll
    for (int i = 0; i < 8; i++) {
        int row = row0 + ty + 16 * i;
        if (row >= M) continue;
        int cr = rowIdx ? rowIdx[row] : row;
#pragma unroll
        for (int j = 0; j < 8; j++) {
            int col = tx + 16 * j;
            float v = acc[i][j];
            if (useBias && bias) v += bias[col];
            if (relu) v = fmaxf(v, 0.f);
            Cout[(size_t)cr * ldcO + colOff + col] = v;
        }
    }
}

// ---------------- launch ----------------
extern "C" void kernel_launch(void* const* d_in, const int* in_sizes, int n_in,
                              void* d_out, int out_size) {
    const int*   edge_index   = (const int*)d_in[0];
    const int*   edge_type    = (const int*)d_in[1];
    const int*   node_indices = (const int*)d_in[2];
    const float* file_feats   = (const float*)d_in[3];
    const int*   file_idx     = (const int*)d_in[4];    // JAX x64 disabled -> int32
    const float* domain_feats = (const float*)d_in[5];
    const int*   domain_idx   = (const int*)d_in[6];
    const float* ip_feats     = (const float*)d_in[7];
    const int*   ip_idx       = (const int*)d_in[8];
    const float* fallback     = (const float*)d_in[9];
    const float* Wf  = (const float*)d_in[10];
    const float* bf  = (const float*)d_in[11];
    const float* Wd  = (const float*)d_in[12];
    const float* bd  = (const float*)d_in[13];
    const float* Wi  = (const float*)d_in[14];
    const float* bi  = (const float*)d_in[15];
    const float* comp1  = (const float*)d_in[16];
    const float* bases1 = (const float*)d_in[17];
    const float* root1  = (const float*)d_in[18];
    const float* bias1  = (const float*)d_in[19];
    const float* comp2  = (const float*)d_in[20];
    const float* bases2 = (const float*)d_in[21];
    const float* root2  = (const float*)d_in[22];
    const float* bias2  = (const float*)d_in[23];
    const float* ln1_g  = (const float*)d_in[24];
    const float* ln1_b  = (const float*)d_in[25];
    const float* ln2_g  = (const float*)d_in[26];
    const float* ln2_b  = (const float*)d_in[27];
    const float* Wc1 = (const float*)d_in[28];
    const float* bc1 = (const float*)d_in[29];
    const float* Wc2 = (const float*)d_in[30];
    const float* bc2 = (const float*)d_in[31];
    float* out = (float*)d_out;

    float *px, *pacc, *pxw, *pW, *phsel;
    cudaGetSymbolAddress((void**)&px,    g_x);
    cudaGetSymbolAddress((void**)&pacc,  g_acc);
    cudaGetSymbolAddress((void**)&pxw,   g_xw);
    cudaGetSymbolAddress((void**)&pW,    g_W);
    cudaGetSymbolAddress((void**)&phsel, g_hsel);

    // ---- build node features ----
    k_copy_x<<<(Nn * Dd / 4 + 255) / 256, 256>>>(fallback);
    gemm_k<<<dim3(157, 1), 256>>>(file_feats,   nullptr, 20000, 256, Wf,
                                  px, Dd, nullptr, -1, bf, 0, file_idx);
    gemm_k<<<dim3(118, 1), 256>>>(domain_feats, nullptr, 15000, 128, Wd,
                                  px, Dd, nullptr, -1, bd, 0, domain_idx);
    gemm_k<<<dim3(79, 1), 256>>>(ip_feats,      nullptr, 10000, 64,  Wi,
                                  px, Dd, nullptr, -1, bi, 0, ip_idx);

    // ---- edge counts (layer-independent) ----
    k_zero_cnt<<<(Rr * Nn + 255) / 256, 256>>>();
    k_count<<<(Ee + 255) / 256, 256>>>(edge_index, edge_type);
    k_inv<<<(Rr * Nn + 255) / 256, 256>>>();

    int gemmRows = (Nn + 127) / 128;  // 391

    // ---- layer 1 ----
    k_build_W<<<((Rr + 1) * Dd * Dd + 255) / 256, 256>>>(comp1, bases1, root1);
    gemm_k<<<dim3(gemmRows, Rr + 1), 256>>>(px, nullptr, Nn, 128, pW,
                                            pxw, Rr * Dd, pacc, Rr, bias1, 0, nullptr);
    k_scatter<<<(Ee * 32) / 256, 256>>>(edge_index, edge_type);
    k_ln<<<(Nn * 32 + 255) / 256, 256>>>(ln1_g, ln1_b, 1);

    // ---- layer 2 ----
    k_build_W<<<((Rr + 1) * Dd * Dd + 255) / 256, 256>>>(comp2, bases2, root2);
    gemm_k<<<dim3(gemmRows, Rr + 1), 256>>>(px, nullptr, Nn, 128, pW,
                                            pxw, Rr * Dd, pacc, Rr, bias2, 0, nullptr);
    k_scatter<<<(Ee * 32) / 256, 256>>>(edge_index, edge_type);
    k_ln<<<(Nn * 32 + 255) / 256, 256>>>(ln2_g, ln2_b, 0);

    // ---- classifier ----
    gemm_k<<<dim3((NSEL + 127) / 128, 1), 256>>>(px, node_indices, NSEL, 128, Wc1,
                                                 phsel, Dd, nullptr, -1, bc1, 1, nullptr);
    k_final<<<(NSEL * NCc + 255) / 256, 256>>>(Wc2, bc2, out);
}

// round 3
// speedup vs baseline: 2.0137x; 2.0137x over previous
#include <cuda_runtime.h>
#include <cuda_bf16.h>

// Problem constants
#define Nn    50000
#define Dd    128
#define Rr    10
#define Ee    800000
#define NSEL  8192
#define NCc   12

// ---------------- device scratch (static allocations only) ----------------
__device__ float g_x[Nn * Dd];                       // 25.6 MB  current node features
__device__ float g_acc[Nn * Dd];                     // 25.6 MB  conv accumulator
__device__ float g_xw[(size_t)Nn * Rr * Dd];         // 256 MB   x @ W[r] for r=0..9
__device__ float g_W[(Rr + 1) * Dd * Dd];            // 0.7 MB   W[0..9] + root in slot 10
__device__ int   g_icnt[Rr * Nn];                    // 2 MB     per-(r,dst) edge counts
__device__ float g_inv[Rr * Nn];                     // 2 MB     1/max(cnt,1)
__device__ float g_hsel[NSEL * Dd];                  // 4 MB     classifier hidden

// ---------------- small kernels ----------------
__global__ void k_copy_x(const float* __restrict__ src) {
    int i = blockIdx.x * blockDim.x + threadIdx.x;
    if (i < Nn * Dd / 4) ((float4*)g_x)[i] = ((const float4*)src)[i];
}

__global__ void k_build_W(const float* __restrict__ comp,
                          const float* __restrict__ bases,
                          const float* __restrict__ root) {
    int i = blockIdx.x * blockDim.x + threadIdx.x;
    if (i >= (Rr + 1) * Dd * Dd) return;
    int slot = i >> 14;
    int idx  = i & 16383;
    float v;
    if (slot < Rr) {
        v = 0.f;
#pragma unroll
        for (int b = 0; b < 4; b++)
            v += comp[slot * 4 + b] * bases[b * Dd * Dd + idx];
    } else {
        v = root[idx];
    }
    g_W[i] = v;
}

__global__ void k_zero_cnt() {
    int i = blockIdx.x * blockDim.x + threadIdx.x;
    if (i < Rr * Nn) g_icnt[i] = 0;
}

__global__ void k_count(const int* __restrict__ ei, const int* __restrict__ et) {
    int e = blockIdx.x * blockDim.x + threadIdx.x;
    if (e >= Ee) return;
    atomicAdd(&g_icnt[et[e] * Nn + ei[Ee + e]], 1);
}

__global__ void k_inv() {
    int i = blockIdx.x * blockDim.x + threadIdx.x;
    if (i < Rr * Nn) g_inv[i] = 1.0f / fmaxf((float)g_icnt[i], 1.0f);
}

// one warp per edge; 128 floats = 32 lanes x float4; vector reduction into L2-resident acc
__global__ void k_scatter(const int* __restrict__ ei, const int* __restrict__ et) {
    int gt = blockIdx.x * blockDim.x + threadIdx.x;
    int e = gt >> 5;
    if (e >= Ee) return;
    int lane = gt & 31;
    int s = ei[e], t = ei[Ee + e], r = et[e];
    float w = g_inv[r * Nn + t];
    float4 v = *(const float4*)(g_xw + (size_t)s * (Rr * Dd) + r * Dd + lane * 4);
    v.x *= w; v.y *= w; v.z *= w; v.w *= w;
    float* p = g_acc + t * Dd + lane * 4;
    asm volatile("red.global.add.v4.f32 [%0], {%1,%2,%3,%4};"
                 :: "l"(p), "f"(v.x), "f"(v.y), "f"(v.z), "f"(v.w) : "memory");
}

// one warp per node: LayerNorm (+optional ReLU), g_acc -> g_x
__global__ void k_ln(const float* __restrict__ g, const float* __restrict__ b, int relu) {
    int gt = blockIdx.x * blockDim.x + threadIdx.x;
    int node = gt >> 5;
    if (node >= Nn) return;
    int lane = gt & 31;
    float4 v = ((const float4*)g_acc)[node * 32 + lane];
    float s = v.x + v.y + v.z + v.w;
    float q = v.x * v.x + v.y * v.y + v.z * v.z + v.w * v.w;
#pragma unroll
    for (int o = 16; o; o >>= 1) {
        s += __shfl_xor_sync(0xffffffffu, s, o);
        q += __shfl_xor_sync(0xffffffffu, q, o);
    }
    float mean = s * (1.f / 128.f);
    float var  = q * (1.f / 128.f) - mean * mean;
    float rstd = rsqrtf(var + 1e-5f);
    float4 gg = ((const float4*)g)[lane];
    float4 bb = ((const float4*)b)[lane];
    float4 o4;
    o4.x = (v.x - mean) * rstd * gg.x + bb.x;
    o4.y = (v.y - mean) * rstd * gg.y + bb.y;
    o4.z = (v.z - mean) * rstd * gg.z + bb.z;
    o4.w = (v.w - mean) * rstd * gg.w + bb.w;
    if (relu) {
        o4.x = fmaxf(o4.x, 0.f); o4.y = fmaxf(o4.y, 0.f);
        o4.z = fmaxf(o4.z, 0.f); o4.w = fmaxf(o4.w, 0.f);
    }
    ((float4*)g_x)[node * 32 + lane] = o4;
}

// final tiny GEMM: out[i,c] = hsel[i,:] @ Wc2[:,c] + bc2[c]
__global__ void k_final(const float* __restrict__ W, const float* __restrict__ b,
                        float* __restrict__ out) {
    int gt = blockIdx.x * blockDim.x + threadIdx.x;
    if (gt >= NSEL * NCc) return;
    int i = gt / NCc, c = gt % NCc;
    const float* hr = g_hsel + i * Dd;
    float s = b[c];
#pragma unroll 8
    for (int k = 0; k < Dd; k++) s += hr[k] * W[k * NCc + c];
    out[gt] = s;
}

// ---------------- tf32 tensor-core GEMM ----------------
__device__ __forceinline__ unsigned f2tf(float f) {
    unsigned u;
    asm("cvt.rna.tf32.f32 %0, %1;" : "=r"(u) : "f"(f));
    return u;
}

__device__ __forceinline__ void mma_tf32(float c[4], const unsigned a[4], const unsigned b[2]) {
    asm volatile("mma.sync.aligned.m16n8k8.row.col.f32.tf32.tf32.f32 "
                 "{%0,%1,%2,%3}, {%4,%5,%6,%7}, {%8,%9}, {%0,%1,%2,%3};"
                 : "+f"(c[0]), "+f"(c[1]), "+f"(c[2]), "+f"(c[3])
                 : "r"(a[0]), "r"(a[1]), "r"(a[2]), "r"(a[3]), "r"(b[0]), "r"(b[1]));
}

// C tile 128 rows x 128 cols, 256 threads = 8 warps (4m x 2n), warp tile 32x64.
// N is always 128. K multiple of 32. grid.y selects weight slot (B + y*K*128);
// y==rootY routes to Croot (+bias). aIdx: gather A rows. rowIdx: scatter C rows.
__global__ void __launch_bounds__(256)
tgemm(const float* __restrict__ A, const int* __restrict__ aIdx,
      int M, int K,
      const float* __restrict__ B,
      float* __restrict__ C, int ldc,
      float* __restrict__ Croot, int rootY,
      const float* __restrict__ bias, int relu,
      const int* __restrict__ rowIdx) {
    int y = blockIdx.y;
    const float* Bz = B + (size_t)y * K * 128;
    int row0 = blockIdx.x * 128;

    __shared__ unsigned As[128][36];   // stride 36: frag-read bank = (4m+k)&31, conflict-free
    __shared__ unsigned Bs[32][136];   // stride 136: frag-read bank = (8k+n)&31, conflict-free

    float acc[2][8][4];
#pragma unroll
    for (int mt = 0; mt < 2; mt++)
#pragma unroll
        for (int nt = 0; nt < 8; nt++)
#pragma unroll
            for (int q = 0; q < 4; q++) acc[mt][nt][q] = 0.f;

    int tid = threadIdx.x;
    int lane = tid & 31, wid = tid >> 5;
    int wm = (wid >> 1) * 32;   // warp row offset
    int wn = (wid & 1) * 64;    // warp col offset

    for (int kb = 0; kb < K; kb += 32) {
        // A tile: 128 rows x 32 cols = 1024 float4
#pragma unroll
        for (int it = 0; it < 4; it++) {
            int idx = tid + it * 256;
            int m = idx >> 3;
            int kq = (idx & 7) * 4;
            float4 v = make_float4(0.f, 0.f, 0.f, 0.f);
            int row = row0 + m;
            if (row < M) {
                int ar = aIdx ? aIdx[row] : row;
                v = *(const float4*)&A[(size_t)ar * K + kb + kq];
            }
            As[m][kq + 0] = f2tf(v.x);
            As[m][kq + 1] = f2tf(v.y);
            As[m][kq + 2] = f2tf(v.z);
            As[m][kq + 3] = f2tf(v.w);
        }
        // B tile: 32 rows (k) x 128 cols (n) = 1024 float4
#pragma unroll
        for (int it = 0; it < 4; it++) {
            int idx = tid + it * 256;
            int k = idx >> 5;
            int nq = (idx & 31) * 4;
            float4 v = *(const float4*)&Bz[(size_t)(kb + k) * 128 + nq];
            Bs[k][nq + 0] = f2tf(v.x);
            Bs[k][nq + 1] = f2tf(v.y);
            Bs[k][nq + 2] = f2tf(v.z);
            Bs[k][nq + 3] = f2tf(v.w);
        }
        __syncthreads();

#pragma unroll
        for (int ks = 0; ks < 4; ks++) {
            int k0 = ks * 8;
            unsigned af[2][4];
#pragma unroll
            for (int mt = 0; mt < 2; mt++) {
                int r = wm + mt * 16 + (lane >> 2);
                int c = k0 + (lane & 3);
                af[mt][0] = As[r][c];
                af[mt][1] = As[r + 8][c];
                af[mt][2] = As[r][c + 4];
                af[mt][3] = As[r + 8][c + 4];
            }
#pragma unroll
            for (int nt = 0; nt < 8; nt++) {
                unsigned bf[2];
                int br = k0 + (lane & 3);
                int bc = wn + nt * 8 + (lane >> 2);
                bf[0] = Bs[br][bc];
                bf[1] = Bs[br + 4][bc];
                mma_tf32(acc[0][nt], af[0], bf);
                mma_tf32(acc[1][nt], af[1], bf);
            }
        }
        __syncthreads();
    }

    bool isRoot = (y == rootY);
    float* Cout = isRoot ? Croot : C;
    int ldcO   = isRoot ? 128 : ldc;
    int colOff = isRoot ? 0   : y * 128;
    bool useBias = (rootY < 0) || isRoot;

#pragma unroll
    for (int mt = 0; mt < 2; mt++) {
#pragma unroll
        for (int h = 0; h < 2; h++) {
            int row = row0 + wm + mt * 16 + (lane >> 2) + h * 8;
            if (row >= M) continue;
            int cr = rowIdx ? rowIdx[row] : row;
#pragma unroll
            for (int nt = 0; nt < 8; nt++) {
                int col = wn + nt * 8 + 2 * (lane & 3);
                float v0 = acc[mt][nt][h * 2 + 0];
                float v1 = acc[mt][nt][h * 2 + 1];
                if (useBias && bias) { v0 += bias[col]; v1 += bias[col + 1]; }
                if (relu) { v0 = fmaxf(v0, 0.f); v1 = fmaxf(v1, 0.f); }
                *(float2*)&Cout[(size_t)cr * ldcO + colOff + col] = make_float2(v0, v1);
            }
        }
    }
}

// ---------------- launch ----------------
extern "C" void kernel_launch(void* const* d_in, const int* in_sizes, int n_in,
                              void* d_out, int out_size) {
    const int*   edge_index   = (const int*)d_in[0];
    const int*   edge_type    = (const int*)d_in[1];
    const int*   node_indices = (const int*)d_in[2];
    const float* file_feats   = (const float*)d_in[3];
    const int*   file_idx     = (const int*)d_in[4];    // JAX x64 disabled -> int32
    const float* domain_feats = (const float*)d_in[5];
    const int*   domain_idx   = (const int*)d_in[6];
    const float* ip_feats     = (const float*)d_in[7];
    const int*   ip_idx       = (const int*)d_in[8];
    const float* fallback     = (const float*)d_in[9];
    const float* Wf  = (const float*)d_in[10];
    const float* bf  = (const float*)d_in[11];
    const float* Wd  = (const float*)d_in[12];
    const float* bd  = (const float*)d_in[13];
    const float* Wi  = (const float*)d_in[14];
    const float* bi  = (const float*)d_in[15];
    const float* comp1  = (const float*)d_in[16];
    const float* bases1 = (const float*)d_in[17];
    const float* root1  = (const float*)d_in[18];
    const float* bias1  = (const float*)d_in[19];
    const float* comp2  = (const float*)d_in[20];
    const float* bases2 = (const float*)d_in[21];
    const float* root2  = (const float*)d_in[22];
    const float* bias2  = (const float*)d_in[23];
    const float* ln1_g  = (const float*)d_in[24];
    const float* ln1_b  = (const float*)d_in[25];
    const float* ln2_g  = (const float*)d_in[26];
    const float* ln2_b  = (const float*)d_in[27];
    const float* Wc1 = (const float*)d_in[28];
    const float* bc1 = (const float*)d_in[29];
    const float* Wc2 = (const float*)d_in[30];
    const float* bc2 = (const float*)d_in[31];
    float* out = (float*)d_out;

    float *px, *pacc, *pxw, *pW, *phsel;
    cudaGetSymbolAddress((void**)&px,    g_x);
    cudaGetSymbolAddress((void**)&pacc,  g_acc);
    cudaGetSymbolAddress((void**)&pxw,   g_xw);
    cudaGetSymbolAddress((void**)&pW,    g_W);
    cudaGetSymbolAddress((void**)&phsel, g_hsel);

    // ---- build node features ----
    k_copy_x<<<(Nn * Dd / 4 + 255) / 256, 256>>>(fallback);
    tgemm<<<dim3(157, 1), 256>>>(file_feats,   nullptr, 20000, 256, Wf,
                                 px, Dd, nullptr, -1, bf, 0, file_idx);
    tgemm<<<dim3(118, 1), 256>>>(domain_feats, nullptr, 15000, 128, Wd,
                                 px, Dd, nullptr, -1, bd, 0, domain_idx);
    tgemm<<<dim3(79, 1), 256>>>(ip_feats,      nullptr, 10000, 64,  Wi,
                                 px, Dd, nullptr, -1, bi, 0, ip_idx);

    // ---- edge counts (layer-independent) ----
    k_zero_cnt<<<(Rr * Nn + 255) / 256, 256>>>();
    k_count<<<(Ee + 255) / 256, 256>>>(edge_index, edge_type);
    k_inv<<<(Rr * Nn + 255) / 256, 256>>>();

    int gemmRows = (Nn + 127) / 128;  // 391

    // ---- layer 1 ----
    k_build_W<<<((Rr + 1) * Dd * Dd + 255) / 256, 256>>>(comp1, bases1, root1);
    tgemm<<<dim3(gemmRows, Rr + 1), 256>>>(px, nullptr, Nn, 128, pW,
                                           pxw, Rr * Dd, pacc, Rr, bias1, 0, nullptr);
    k_scatter<<<(Ee * 32) / 256, 256>>>(edge_index, edge_type);
    k_ln<<<(Nn * 32 + 255) / 256, 256>>>(ln1_g, ln1_b, 1);

    // ---- layer 2 ----
    k_build_W<<<((Rr + 1) * Dd * Dd + 255) / 256, 256>>>(comp2, bases2, root2);
    tgemm<<<dim3(gemmRows, Rr + 1), 256>>>(px, nullptr, Nn, 128, pW,
                                           pxw, Rr * Dd, pacc, Rr, bias2, 0, nullptr);
    k_scatter<<<(Ee * 32) / 256, 256>>>(edge_index, edge_type);
    k_ln<<<(Nn * 32 + 255) / 256, 256>>>(ln2_g, ln2_b, 0);

    // ---- classifier ----
    tgemm<<<dim3((NSEL + 127) / 128, 1), 256>>>(px, node_indices, NSEL, 128, Wc1,
                                                phsel, Dd, nullptr, -1, bc1, 1, nullptr);
    k_final<<<(NSEL * NCc + 255) / 256, 256>>>(Wc2, bc2, out);
}